// round 5
// baseline (speedup 1.0000x reference)
#include <cuda_runtime.h>
#include <cuda_bf16.h>

// ChamferDistance: B=8, N=4096, D=3.
// Round 5: same packed-FFMA2 inner loop; push residency to 8 blocks/SM
// (launch_bounds(128,8), TSPLIT=32 -> 2048 blocks) and replace the
// distinct-slot cross-split combine with deterministic encoded atomicMax
// (min over floats via order-reversing uint encode; exact & order-free),
// shrinking the serialized combine tail 16x.

#define CD_B 8
#define CD_N 4096
#define CD_TPB 128
#define CD_Q 8
#define CD_QBLK (CD_TPB * CD_Q)          // 1024 queries per block
#define CD_NQB (CD_N / CD_QBLK)          // 4
#define CD_TSPLIT 32
#define CD_TPTS (CD_N / CD_TSPLIT)       // 128 targets per block
#define CD_TPAIRS (CD_TPTS / 2)          // 64 packed pairs
#define CD_NGRP (2 * CD_B * CD_NQB)      // 64 groups of CD_TSPLIT blocks

// Encoded per-query running min: key = ~bits(max(v,0)); atomicMax == float min.
// Zero-initialized by CUDA runtime; reset to 0 in-kernel for graph replay.
__device__ unsigned int g_qmin[CD_NGRP][CD_QBLK];
__device__ float g_part[CD_NGRP];
__device__ unsigned int g_gcnt[CD_NGRP];
__device__ unsigned int g_fcnt;

typedef unsigned long long u64;

__device__ __forceinline__ u64 pack2(float v) {
    u64 r;
    unsigned int u = __float_as_uint(v);
    asm("mov.b64 %0, {%1, %1};" : "=l"(r) : "r"(u));
    return r;
}

__device__ __forceinline__ u64 fma2(u64 a, u64 b, u64 c) {
    u64 d;
    asm("fma.rn.f32x2 %0, %1, %2, %3;" : "=l"(d) : "l"(a), "l"(b), "l"(c));
    return d;
}

__device__ __forceinline__ void unpack2(u64 v, float& lo, float& hi) {
    unsigned int l, h;
    asm("mov.b64 {%0, %1}, %2;" : "=r"(l), "=r"(h) : "l"(v));
    lo = __uint_as_float(l);
    hi = __uint_as_float(h);
}

__global__ __launch_bounds__(CD_TPB, 8)
void chamfer_kernel(const float* __restrict__ p1,
                    const float* __restrict__ p2,
                    float* __restrict__ out) {
    __shared__ float4 sy[CD_TPTS];      // pair-interleaved tile (2KB)
    __shared__ float s_xd[CD_Q][CD_TPB];
    __shared__ float red[CD_TPB];
    __shared__ int s_flag;

    const int tid  = threadIdx.x;
    const int ts   = blockIdx.x % CD_TSPLIT;
    const int qblk = blockIdx.x / CD_TSPLIT;
    const int b    = blockIdx.y;
    const int dir  = blockIdx.z;
    const int grp  = (dir * CD_B + b) * CD_NQB + qblk;

    const float* __restrict__ src = dir ? p2 : p1;
    const float* __restrict__ tgt = dir ? p1 : p2;

    // Q=8 query points; fold -2 into packed coords; xd parked in smem.
    u64 xq0[CD_Q], xq1[CD_Q], xq2[CD_Q];
    float mlo[CD_Q], mhi[CD_Q];
    #pragma unroll
    for (int q = 0; q < CD_Q; q++) {
        const int i = qblk * CD_QBLK + q * CD_TPB + tid;
        const float* xp = src + ((size_t)b * CD_N + i) * 3;
        const float x0 = xp[0], x1 = xp[1], x2 = xp[2];
        s_xd[q][tid] = x0 * x0 + x1 * x1 + x2 * x2;
        xq0[q] = pack2(-2.0f * x0);
        xq1[q] = pack2(-2.0f * x1);
        xq2[q] = pack2(-2.0f * x2);
        mlo[q] = 3.402823466e38f;
        mhi[q] = 3.402823466e38f;
    }

    // One target pair per thread (first 64 threads) into the tile.
    if (tid < CD_TPAIRS) {
        const float* yp = tgt + ((size_t)b * CD_N + ts * CD_TPTS + 2 * tid) * 3;
        float e0 = yp[0], e1 = yp[1], e2 = yp[2];
        float o0 = yp[3], o1 = yp[4], o2 = yp[5];
        sy[2 * tid]     = make_float4(e0, o0, e1, o1);
        sy[2 * tid + 1] = make_float4(e2, o2,
                                      e0 * e0 + e1 * e1 + e2 * e2,
                                      o0 * o0 + o1 * o1 + o2 * o2);
    }
    __syncthreads();

    const ulonglong2* __restrict__ syu = reinterpret_cast<const ulonglong2*>(sy);

    #pragma unroll 4
    for (int p = 0; p < CD_TPAIRS; p++) {
        ulonglong2 A  = syu[2 * p];      // y0 pair, y1 pair
        ulonglong2 Bv = syu[2 * p + 1];  // y2 pair, yd pair
        #pragma unroll
        for (int q = 0; q < CD_Q; q++) {
            u64 d = fma2(xq2[q], Bv.x, Bv.y);
            d = fma2(xq1[q], A.y, d);
            d = fma2(xq0[q], A.x, d);
            float dlo, dhi;
            unpack2(d, dlo, dhi);
            mlo[q] = fminf(mlo[q], dlo);
            mhi[q] = fminf(mhi[q], dhi);
        }
    }

    // Deterministic cross-split min via encoded atomicMax.
    // v >= 0 after clamp; key = ~bits(v) is strictly order-reversing, so
    // atomicMax(key) == float min, independent of arrival order.
    #pragma unroll
    for (int q = 0; q < CD_Q; q++) {
        float v = fmaxf(fminf(mlo[q], mhi[q]) + s_xd[q][tid], 0.0f);
        atomicMax(&g_qmin[grp][q * CD_TPB + tid], ~__float_as_uint(v));
    }

    __threadfence();
    if (tid == 0) {
        unsigned int t = atomicAdd(&g_gcnt[grp], 1u);
        s_flag = (t == CD_TSPLIT - 1);
    }
    __syncthreads();

    if (s_flag) {
        // Last block of the group: decode 1024 mins, fixed-order sum; reset slots.
        float acc = 0.0f;
        #pragma unroll
        for (int q = 0; q < CD_Q; q++) {
            const int qi = q * CD_TPB + tid;
            unsigned int key = g_qmin[grp][qi];
            acc += __uint_as_float(~key);
            g_qmin[grp][qi] = 0u;                  // reset for graph replay
        }
        red[tid] = acc;
        __syncthreads();
        #pragma unroll
        for (int s = CD_TPB / 2; s > 0; s >>= 1) {
            if (tid < s) red[tid] += red[tid + s];
            __syncthreads();
        }
        if (tid == 0) {
            g_part[grp] = red[0];
            g_gcnt[grp] = 0;                       // reset for graph replay
            __threadfence();
            unsigned int t = atomicAdd(&g_fcnt, 1u);
            s_flag = (t == CD_NGRP - 1);
        }
        __syncthreads();

        if (s_flag) {
            // Final: fixed-order sum of 64 group partials.
            float v = (tid < CD_NGRP) ? g_part[tid] : 0.0f;
            red[tid] = v;
            __syncthreads();
            #pragma unroll
            for (int s = CD_TPB / 2; s > 0; s >>= 1) {
                if (tid < s) red[tid] += red[tid + s];
                __syncthreads();
            }
            if (tid == 0) {
                out[0] = red[0] * (1.0f / ((float)CD_B * (float)CD_N));
                g_fcnt = 0;                        // reset for graph replay
            }
        }
    }
}

extern "C" void kernel_launch(void* const* d_in, const int* in_sizes, int n_in,
                              void* d_out, int out_size) {
    (void)in_sizes; (void)n_in; (void)out_size;
    const float* p1 = (const float*)d_in[0];
    const float* p2 = (const float*)d_in[1];
    float* out = (float*)d_out;

    dim3 grid(CD_NQB * CD_TSPLIT, CD_B, 2);   // 128 x 8 x 2 = 2048 blocks
    chamfer_kernel<<<grid, CD_TPB>>>(p1, p2, out);
}

// round 7
// speedup vs baseline: 1.0932x; 1.0932x over previous
#include <cuda_runtime.h>
#include <cuda_bf16.h>

// ChamferDistance: B=8, N=4096, D=3.
// Round 7: round-6 failed to compile (min.f32x2 is not a PTX instruction;
// packed f32 covers add/mul/fma only). Same experiment as round 6 otherwise:
// test the register-starvation theory. TPB=64 + launch_bounds(64,12) gives an
// ~85-register budget (Q=8 packed state fits, no forced spills/short
// scheduling) while keeping ~6 warps/SMSP and 2048 blocks. Min done with
// scalar fminf on the two halves of each packed result (FMNMX, alu pipe).
// Combine: deterministic encoded atomicMax + last-block-done fixed-order sums.

#define CD_B 8
#define CD_N 4096
#define CD_TPB 64
#define CD_Q 8
#define CD_QBLK (CD_TPB * CD_Q)          // 512 queries per block
#define CD_NQB (CD_N / CD_QBLK)          // 8
#define CD_TSPLIT 16
#define CD_TPTS (CD_N / CD_TSPLIT)       // 256 targets per block
#define CD_TPAIRS (CD_TPTS / 2)          // 128 packed pairs
#define CD_NGRP (2 * CD_B * CD_NQB)      // 128 groups of CD_TSPLIT blocks

// Encoded per-query running min: key = ~bits(max(v,0)); atomicMax == float min.
__device__ unsigned int g_qmin[CD_NGRP][CD_QBLK];
__device__ float g_part[CD_NGRP];
__device__ unsigned int g_gcnt[CD_NGRP];
__device__ unsigned int g_fcnt;

typedef unsigned long long u64;

__device__ __forceinline__ u64 pack2(float v) {
    u64 r;
    unsigned int u = __float_as_uint(v);
    asm("mov.b64 %0, {%1, %1};" : "=l"(r) : "r"(u));
    return r;
}

__device__ __forceinline__ u64 fma2(u64 a, u64 b, u64 c) {
    u64 d;
    asm("fma.rn.f32x2 %0, %1, %2, %3;" : "=l"(d) : "l"(a), "l"(b), "l"(c));
    return d;
}

__device__ __forceinline__ void unpack2(u64 v, float& lo, float& hi) {
    unsigned int l, h;
    asm("mov.b64 {%0, %1}, %2;" : "=r"(l), "=r"(h) : "l"(v));
    lo = __uint_as_float(l);
    hi = __uint_as_float(h);
}

__global__ __launch_bounds__(CD_TPB, 12)
void chamfer_kernel(const float* __restrict__ p1,
                    const float* __restrict__ p2,
                    float* __restrict__ out) {
    __shared__ float4 sy[CD_TPTS];       // pair-interleaved tile (4KB)
    __shared__ float s_xd[CD_Q][CD_TPB];
    __shared__ float red[CD_TPB];
    __shared__ int s_flag;

    const int tid  = threadIdx.x;
    const int ts   = blockIdx.x % CD_TSPLIT;
    const int qblk = blockIdx.x / CD_TSPLIT;
    const int b    = blockIdx.y;
    const int dir  = blockIdx.z;
    const int grp  = (dir * CD_B + b) * CD_NQB + qblk;

    const float* __restrict__ src = dir ? p2 : p1;
    const float* __restrict__ tgt = dir ? p1 : p2;

    // Q=8 query points; fold -2 into packed coords; xd parked in smem.
    u64 xq0[CD_Q], xq1[CD_Q], xq2[CD_Q];
    float mlo[CD_Q], mhi[CD_Q];
    #pragma unroll
    for (int q = 0; q < CD_Q; q++) {
        const int i = qblk * CD_QBLK + q * CD_TPB + tid;
        const float* xp = src + ((size_t)b * CD_N + i) * 3;
        const float x0 = xp[0], x1 = xp[1], x2 = xp[2];
        s_xd[q][tid] = x0 * x0 + x1 * x1 + x2 * x2;
        xq0[q] = pack2(-2.0f * x0);
        xq1[q] = pack2(-2.0f * x1);
        xq2[q] = pack2(-2.0f * x2);
        mlo[q] = 3.402823466e38f;
        mhi[q] = 3.402823466e38f;
    }

    // Pair-interleaved tile load: 2 pairs per thread (TPAIRS=128, TPB=64).
    #pragma unroll
    for (int p = tid; p < CD_TPAIRS; p += CD_TPB) {
        const float* yp = tgt + ((size_t)b * CD_N + ts * CD_TPTS + 2 * p) * 3;
        float e0 = yp[0], e1 = yp[1], e2 = yp[2];
        float o0 = yp[3], o1 = yp[4], o2 = yp[5];
        sy[2 * p]     = make_float4(e0, o0, e1, o1);
        sy[2 * p + 1] = make_float4(e2, o2,
                                    e0 * e0 + e1 * e1 + e2 * e2,
                                    o0 * o0 + o1 * o1 + o2 * o2);
    }
    __syncthreads();

    const ulonglong2* __restrict__ syu = reinterpret_cast<const ulonglong2*>(sy);

    #pragma unroll 4
    for (int p = 0; p < CD_TPAIRS; p++) {
        ulonglong2 A  = syu[2 * p];      // y0 pair, y1 pair
        ulonglong2 Bv = syu[2 * p + 1];  // y2 pair, yd pair
        #pragma unroll
        for (int q = 0; q < CD_Q; q++) {
            u64 d = fma2(xq2[q], Bv.x, Bv.y);
            d = fma2(xq1[q], A.y, d);
            d = fma2(xq0[q], A.x, d);
            float dlo, dhi;
            unpack2(d, dlo, dhi);
            mlo[q] = fminf(mlo[q], dlo);
            mhi[q] = fminf(mhi[q], dhi);
        }
    }

    // Deterministic cross-split min via encoded atomicMax (order-free).
    #pragma unroll
    for (int q = 0; q < CD_Q; q++) {
        float v = fmaxf(fminf(mlo[q], mhi[q]) + s_xd[q][tid], 0.0f);
        atomicMax(&g_qmin[grp][q * CD_TPB + tid], ~__float_as_uint(v));
    }

    __threadfence();
    if (tid == 0) {
        unsigned int t = atomicAdd(&g_gcnt[grp], 1u);
        s_flag = (t == CD_TSPLIT - 1);
    }
    __syncthreads();

    if (s_flag) {
        // Last block of the group: decode mins, fixed-order sum; reset slots.
        float acc = 0.0f;
        #pragma unroll
        for (int q = 0; q < CD_Q; q++) {
            const int qi = q * CD_TPB + tid;
            unsigned int key = g_qmin[grp][qi];
            acc += __uint_as_float(~key);
            g_qmin[grp][qi] = 0u;                  // reset for graph replay
        }
        red[tid] = acc;
        __syncthreads();
        #pragma unroll
        for (int s = CD_TPB / 2; s > 0; s >>= 1) {
            if (tid < s) red[tid] += red[tid + s];
            __syncthreads();
        }
        if (tid == 0) {
            g_part[grp] = red[0];
            g_gcnt[grp] = 0;                       // reset for graph replay
            __threadfence();
            unsigned int t = atomicAdd(&g_fcnt, 1u);
            s_flag = (t == CD_NGRP - 1);
        }
        __syncthreads();

        if (s_flag) {
            // Final: fixed-order sum of 128 group partials (2 per thread).
            float v = g_part[tid] + g_part[tid + CD_TPB];
            red[tid] = v;
            __syncthreads();
            #pragma unroll
            for (int s = CD_TPB / 2; s > 0; s >>= 1) {
                if (tid < s) red[tid] += red[tid + s];
                __syncthreads();
            }
            if (tid == 0) {
                out[0] = red[0] * (1.0f / ((float)CD_B * (float)CD_N));
                g_fcnt = 0;                        // reset for graph replay
            }
        }
    }
}

extern "C" void kernel_launch(void* const* d_in, const int* in_sizes, int n_in,
                              void* d_out, int out_size) {
    (void)in_sizes; (void)n_in; (void)out_size;
    const float* p1 = (const float*)d_in[0];
    const float* p2 = (const float*)d_in[1];
    float* out = (float*)d_out;

    dim3 grid(CD_NQB * CD_TSPLIT, CD_B, 2);   // 128 x 8 x 2 = 2048 blocks
    chamfer_kernel<<<grid, CD_TPB>>>(p1, p2, out);
}